// round 6
// baseline (speedup 1.0000x reference)
#include <cuda_runtime.h>
#include <math.h>

#define NB   8
#define CIN  16
#define HH   32
#define WW   32
#define OC   64
#define RDIM 144
#define OH   30
#define OW   30

// Packed fp32x2 FMA (sm_100+): d = a*b + d lanewise
#define FMA2(d, a, b) \
    asm("fma.rn.f32x2 %0, %1, %2, %0;" : "+l"(d) : "l"(a), "l"(b))
#define PACK2(d, v) \
    asm("mov.b64 %0, {%1, %1};" : "=l"(d) : "r"(__float_as_uint(v)))

__global__ __launch_bounds__(256, 1)
void fused_kernel(const float* __restrict__ x,
                  const float* __restrict__ k,
                  const float* __restrict__ bias,
                  const float* __restrict__ dxp,
                  const float* __restrict__ dwp,
                  float* __restrict__ out) {
    __shared__ float ws[RDIM][OC];    // exp(k+5): 36864 B
    __shared__ float xc[CIN][4][WW];  // clamped x+5 slab: 8192 B
    __shared__ float srow[4][WW];     // channel-sums of raw x: 512 B
    __shared__ float part[2][OC];     // koff partials: 512 B
    __shared__ float koff[OC];        // 256 B
    __shared__ float sdw;
    // total ~46.3 KB < 48 KB

    const int n  = blockIdx.y;
    const int r0 = blockIdx.x * 2;    // output row base
    const int t  = threadIdx.x;
    const int lane = t & 31;
    const int wid  = t >> 5;

    // --- Stage all weights with fused exp: t -> (rsub = t>>6, oci = t&63) ---
    {
        const int oci  = t & 63;
        const int rsub = t >> 6;      // 0..3
        #pragma unroll
        for (int rb = 0; rb < RDIM; rb += 4)
            ws[rb + rsub][oci] = expf(k[(rb + rsub) * OC + oci] + 5.0f);
    }
    // --- Stage x slab (t<128) / koff partials (t>=128) ---
    if (t < 128) {
        const int srw = t >> 5, w = t & 31;
        const float* xp = x + ((size_t)n * CIN * HH + (r0 + srw)) * WW + w;
        float s = 0.0f;
        #pragma unroll
        for (int c = 0; c < CIN; c++) {
            float v = xp[(size_t)c * HH * WW];
            s += v;
            xc[c][srw][w] = fmaxf(v + 5.0f, 1e-12f);
        }
        srow[srw][w] = s;
    } else {
        const int u = t - 128;        // 0..127
        const int oci = u & 63, half = u >> 6;
        float s = 0.0f;
        #pragma unroll
        for (int j = 0; j < 72; j++)
            s += k[(half * 72 + j) * OC + oci];
        part[half][oci] = s;
    }
    if (t == 0) sdw = dwp[0];
    __syncthreads();
    if (t < OC)
        koff[t] = bias[t] - dxp[0] * (part[0][t] + part[1][t]);
    __syncthreads();

    // --- Main loop: lane = rowbit*16 + colpair; warp = oc octet ---
    const int cp   = lane & 15;              // col pair (15 inactive)
    const int rowb = lane >> 4;              // 0..1
    const int ocg  = wid * 8;                // warp-uniform oc base
    const int c0   = (cp < 15) ? 2 * cp : 28;
    const bool active = (cp < 15);

    unsigned long long acc[2][4];
    #pragma unroll
    for (int j = 0; j < 2; j++)
        #pragma unroll
        for (int q = 0; q < 4; q++) acc[j][q] = 0ull;

    #pragma unroll
    for (int kh = 0; kh < 3; kh++) {
        // software-pipelined x loads: prefetch next c while FMAs run on current
        float2 xa = *(const float2*)&xc[0][rowb + kh][c0];
        float2 xb = *(const float2*)&xc[0][rowb + kh][c0 + 2];
        #pragma unroll
        for (int c = 0; c < CIN; c++) {
            float2 na, nb;
            if (c + 1 < CIN) {
                na = *(const float2*)&xc[c + 1][rowb + kh][c0];
                nb = *(const float2*)&xc[c + 1][rowb + kh][c0 + 2];
            }
            unsigned long long p[4];
            PACK2(p[0], xa.x);
            PACK2(p[1], xa.y);
            PACK2(p[2], xb.x);
            PACK2(p[3], xb.y);
            #pragma unroll
            for (int kw = 0; kw < 3; kw++) {
                const ulonglong2* wp =
                    (const ulonglong2*)&ws[(kh * 3 + kw) * CIN + c][ocg];
                const ulonglong2 w01 = wp[0];
                const ulonglong2 w23 = wp[1];
                FMA2(acc[0][0], p[kw],     w01.x);
                FMA2(acc[0][1], p[kw],     w01.y);
                FMA2(acc[0][2], p[kw],     w23.x);
                FMA2(acc[0][3], p[kw],     w23.y);
                FMA2(acc[1][0], p[kw + 1], w01.x);
                FMA2(acc[1][1], p[kw + 1], w01.y);
                FMA2(acc[1][2], p[kw + 1], w23.x);
                FMA2(acc[1][3], p[kw + 1], w23.y);
            }
            xa = na; xb = nb;
        }
    }

    if (active) {
        float xs0 = 0.0f, xs1 = 0.0f;
        #pragma unroll
        for (int kh = 0; kh < 3; kh++)
            #pragma unroll
            for (int kw = 0; kw < 3; kw++) {
                xs0 += srow[rowb + kh][2 * cp + kw];
                xs1 += srow[rowb + kh][2 * cp + 1 + kw];
            }
        const float dwv = sdw;
        xs0 *= dwv; xs1 *= dwv;

        const int row = r0 + rowb;
        const int col = 2 * cp;
        float* op = out + ((size_t)(n * OC + ocg)) * (OH * OW) + row * OW + col;
        #pragma unroll
        for (int q = 0; q < 4; q++) {
            const float a0lo = __uint_as_float((unsigned)(acc[0][q] & 0xffffffffu));
            const float a0hi = __uint_as_float((unsigned)(acc[0][q] >> 32));
            const float a1lo = __uint_as_float((unsigned)(acc[1][q] & 0xffffffffu));
            const float a1hi = __uint_as_float((unsigned)(acc[1][q] >> 32));
            const float k0 = koff[ocg + 2 * q];
            const float k1 = koff[ocg + 2 * q + 1];
            float2 v0 = make_float2(a0lo - xs0 + k0, a1lo - xs1 + k0);
            float2 v1 = make_float2(a0hi - xs0 + k1, a1hi - xs1 + k1);
            *(float2*)(op + (size_t)(2 * q)     * (OH * OW)) = v0;
            *(float2*)(op + (size_t)(2 * q + 1) * (OH * OW)) = v1;
        }
    }
}

extern "C" void kernel_launch(void* const* d_in, const int* in_sizes, int n_in,
                              void* d_out, int out_size) {
    const float* x    = (const float*)d_in[0];
    const float* k    = (const float*)d_in[1];
    const float* bias = (const float*)d_in[2];
    const float* dx   = (const float*)d_in[3];
    const float* dw   = (const float*)d_in[4];
    float* out = (float*)d_out;

    dim3 grid(OH / 2, NB);   // (15, 8) = 120 blocks, <=1 per SM, uniform
    fused_kernel<<<grid, 256>>>(x, k, bias, dx, dw, out);
}

// round 7
// speedup vs baseline: 1.0239x; 1.0239x over previous
#include <cuda_runtime.h>
#include <math.h>

#define NB   8
#define CIN  16
#define HH   32
#define WW   32
#define OC   64
#define RDIM 144
#define OH   30
#define OW   30

// Packed fp32x2 FMA (sm_100+): d = a*b + d lanewise
#define FMA2(d, a, b) \
    asm("fma.rn.f32x2 %0, %1, %2, %0;" : "+l"(d) : "l"(a), "l"(b))
#define PACK2(d, v) \
    asm("mov.b64 %0, {%1, %1};" : "=l"(d) : "r"(__float_as_uint(v)))

__global__ __launch_bounds__(256, 1)
void fused_kernel(const float* __restrict__ x,
                  const float* __restrict__ k,
                  const float* __restrict__ bias,
                  const float* __restrict__ dxp,
                  const float* __restrict__ dwp,
                  float* __restrict__ out) {
    __shared__ float ws[RDIM][OC];    // exp(k+5): 36864 B
    __shared__ float xc[CIN][4][WW];  // clamped x+5 slab: 8192 B
    __shared__ float srow[4][WW];     // channel-sums of raw x: 512 B
    __shared__ float part[4][OC];     // koff partials: 1024 B
    __shared__ float koff[OC];        // 256 B
    __shared__ float sdw;
    // total ~46.9 KB < 48 KB

    const int n  = blockIdx.y;
    const int r0 = blockIdx.x * 2;    // output row base
    const int t  = threadIdx.x;
    const int lane = t & 31;
    const int wid  = t >> 5;

    // --- Stage all weights with fused exp; fold koff partial into same loads ---
    {
        const int oci  = t & 63;
        const int rsub = t >> 6;      // 0..3
        float ks = 0.0f;
        #pragma unroll
        for (int rb = 0; rb < RDIM; rb += 4) {
            const float kv = k[(rb + rsub) * OC + oci];
            ks += kv;
            ws[rb + rsub][oci] = expf(kv + 5.0f);
        }
        part[rsub][oci] = ks;
    }
    // --- Stage x slab (threads 0..127) ---
    if (t < 128) {
        const int srw = t >> 5, w = t & 31;
        const float* xp = x + ((size_t)n * CIN * HH + (r0 + srw)) * WW + w;
        float s = 0.0f;
        #pragma unroll
        for (int c = 0; c < CIN; c++) {
            float v = xp[(size_t)c * HH * WW];
            s += v;
            xc[c][srw][w] = fmaxf(v + 5.0f, 1e-12f);
        }
        srow[srw][w] = s;
    }
    if (t == 0) sdw = dwp[0];
    __syncthreads();
    if (t < OC)
        koff[t] = bias[t]
                - dxp[0] * (part[0][t] + part[1][t] + part[2][t] + part[3][t]);
    __syncthreads();

    // --- Main loop: lane = rowbit*16 + colpair; warp = oc octet ---
    const int cp   = lane & 15;              // col pair (cp==15 inactive)
    const int rowb = lane >> 4;              // 0..1
    const int ocg  = wid * 8;                // warp-uniform oc base
    const int c0   = (cp < 15) ? 2 * cp : 28;
    const bool active = (cp < 15);

    unsigned long long acc[2][4];
    #pragma unroll
    for (int j = 0; j < 2; j++)
        #pragma unroll
        for (int q = 0; q < 4; q++) acc[j][q] = 0ull;

    #pragma unroll
    for (int kh = 0; kh < 3; kh++) {
        // pipeline fill: iteration c=0's weights + x
        ulonglong2 cw[3][2];
        #pragma unroll
        for (int kw = 0; kw < 3; kw++) {
            const ulonglong2* wp = (const ulonglong2*)&ws[(kh * 3 + kw) * CIN][ocg];
            cw[kw][0] = wp[0];
            cw[kw][1] = wp[1];
        }
        float2 cxa = *(const float2*)&xc[0][rowb + kh][c0];
        float2 cxb = *(const float2*)&xc[0][rowb + kh][c0 + 2];

        #pragma unroll
        for (int c = 0; c < CIN; c++) {
            // --- prefetch EVERYTHING for c+1 before consuming c ---
            const int cn = (c + 1 < CIN) ? c + 1 : c;   // clamped (last iter redundant)
            ulonglong2 nw[3][2];
            #pragma unroll
            for (int kw = 0; kw < 3; kw++) {
                const ulonglong2* wp =
                    (const ulonglong2*)&ws[(kh * 3 + kw) * CIN + cn][ocg];
                nw[kw][0] = wp[0];
                nw[kw][1] = wp[1];
            }
            const float2 nxa = *(const float2*)&xc[cn][rowb + kh][c0];
            const float2 nxb = *(const float2*)&xc[cn][rowb + kh][c0 + 2];

            // --- consume iteration c: 24 FMA2 ---
            unsigned long long p[4];
            PACK2(p[0], cxa.x);
            PACK2(p[1], cxa.y);
            PACK2(p[2], cxb.x);
            PACK2(p[3], cxb.y);
            #pragma unroll
            for (int kw = 0; kw < 3; kw++) {
                FMA2(acc[0][0], p[kw],     cw[kw][0].x);
                FMA2(acc[0][1], p[kw],     cw[kw][0].y);
                FMA2(acc[0][2], p[kw],     cw[kw][1].x);
                FMA2(acc[0][3], p[kw],     cw[kw][1].y);
                FMA2(acc[1][0], p[kw + 1], cw[kw][0].x);
                FMA2(acc[1][1], p[kw + 1], cw[kw][0].y);
                FMA2(acc[1][2], p[kw + 1], cw[kw][1].x);
                FMA2(acc[1][3], p[kw + 1], cw[kw][1].y);
            }

            // rotate (register renaming under full unroll)
            #pragma unroll
            for (int kw = 0; kw < 3; kw++) {
                cw[kw][0] = nw[kw][0];
                cw[kw][1] = nw[kw][1];
            }
            cxa = nxa;
            cxb = nxb;
        }
    }

    if (active) {
        float xs0 = 0.0f, xs1 = 0.0f;
        #pragma unroll
        for (int kh = 0; kh < 3; kh++)
            #pragma unroll
            for (int kw = 0; kw < 3; kw++) {
                xs0 += srow[rowb + kh][2 * cp + kw];
                xs1 += srow[rowb + kh][2 * cp + 1 + kw];
            }
        const float dwv = sdw;
        xs0 *= dwv; xs1 *= dwv;

        const int row = r0 + rowb;
        const int col = 2 * cp;
        float* op = out + ((size_t)(n * OC + ocg)) * (OH * OW) + row * OW + col;
        #pragma unroll
        for (int q = 0; q < 4; q++) {
            const float a0lo = __uint_as_float((unsigned)(acc[0][q] & 0xffffffffu));
            const float a0hi = __uint_as_float((unsigned)(acc[0][q] >> 32));
            const float a1lo = __uint_as_float((unsigned)(acc[1][q] & 0xffffffffu));
            const float a1hi = __uint_as_float((unsigned)(acc[1][q] >> 32));
            const float k0 = koff[ocg + 2 * q];
            const float k1 = koff[ocg + 2 * q + 1];
            float2 v0 = make_float2(a0lo - xs0 + k0, a1lo - xs1 + k0);
            float2 v1 = make_float2(a0hi - xs0 + k1, a1hi - xs1 + k1);
            *(float2*)(op + (size_t)(2 * q)     * (OH * OW)) = v0;
            *(float2*)(op + (size_t)(2 * q + 1) * (OH * OW)) = v1;
        }
    }
}

extern "C" void kernel_launch(void* const* d_in, const int* in_sizes, int n_in,
                              void* d_out, int out_size) {
    const float* x    = (const float*)d_in[0];
    const float* k    = (const float*)d_in[1];
    const float* bias = (const float*)d_in[2];
    const float* dx   = (const float*)d_in[3];
    const float* dw   = (const float*)d_in[4];
    float* out = (float*)d_out;

    dim3 grid(OH / 2, NB);   // (15, 8) = 120 blocks, <=1 per SM, uniform
    fused_kernel<<<grid, 256>>>(x, k, bias, dx, dw, out);
}